// round 10
// baseline (speedup 1.0000x reference)
#include <cuda_runtime.h>
#include <math.h>

#define B_ 512
#define T_ 256
#define N_ 128
#define M_ 256
#define FM_ 1024   // 4*M
#define GRID_LSTM 128

// ---------------- scratch (device globals: allocation-free) ----------------
__device__ float g_r2[(size_t)B_ * N_ * T_];            // [b][n][u]       67 MB
__device__ float g_Xk[(size_t)T_ * B_ * FM_];           // [t][b][4M]     537 MB
__device__ float g_H[(size_t)(T_ + 1) * B_ * M_];       // row-layout hist 135 MB
__device__ float g_S[(size_t)(T_ + 1) * B_ * M_];       // row-layout hist 135 MB
__device__ float g_Ht[(size_t)(T_ + 1) * 16 * M_ * 32]; // [t][bx][m][r]  135 MB
__device__ float g_R1[(size_t)T_ * B_ * T_];            // [tau][b][u]    134 MB
__device__ float g_Wrt[(size_t)M_ * FM_];               // Wr [k][m][gate]  1 MB

// per-bx-group arrival counters (zeroed by k_init each launch -> replay-safe)
__device__ unsigned long long g_arr[16];

__device__ __forceinline__ float sigm(float x) {
    return __fdividef(1.0f, 1.0f + __expf(-x));
}
// accurate tanh (chain): rel err ~1e-6
__device__ __forceinline__ float tanh_e(float x) {
    float a = fabsf(x);
    float e = __expf(-2.0f * a);
    float r = __fdividef(1.0f - e, 1.0f + e);
    return copysignf(r, x);
}
// HW tanh (attention logits only)
__device__ __forceinline__ float tanh_fast(float x) {
    float y;
    asm("tanh.approx.f32 %0, %1;" : "=f"(y) : "f"(x));
    return y;
}

// ---- packed f32x2 helpers (FFMA2: B300, PTX-only path) ----
__device__ __forceinline__ unsigned long long fma2(unsigned long long a,
                                                   unsigned long long b,
                                                   unsigned long long c) {
    unsigned long long d;
    asm("fma.rn.f32x2 %0, %1, %2, %3;" : "=l"(d) : "l"(a), "l"(b), "l"(c));
    return d;
}
__device__ __forceinline__ unsigned long long add2(unsigned long long a,
                                                   unsigned long long b) {
    unsigned long long d;
    asm("add.rn.f32x2 %0, %1, %2;" : "=l"(d) : "l"(a), "l"(b));
    return d;
}
__device__ __forceinline__ unsigned long long dup2(float x) {
    unsigned long long r;
    asm("mov.b64 %0, {%1, %1};" : "=l"(r) : "f"(x));
    return r;
}
__device__ __forceinline__ void unpack2(unsigned long long p, float& lo, float& hi) {
    asm("mov.b64 {%0, %1}, %2;" : "=f"(lo), "=f"(hi) : "l"(p));
}

// ---- init: slot 0 <- (h, s) in both layouts; Wr gate-interleave; reset bars ----
__global__ void k_init(const float* __restrict__ s, const float* __restrict__ h,
                       const float* __restrict__ Wr) {
    int i = blockIdx.x * blockDim.x + threadIdx.x;
    if (i < B_ * M_) {
        g_H[i] = h[i];
        g_S[i] = s[i];
        int b = i >> 8;       // row
        int m = i & 255;      // col
        int bx = b >> 5, r = b & 31;
        g_Ht[((size_t)bx * 256 + m) * 32 + r] = h[i];
    }
    if (i < M_ * FM_) {
        int k = i >> 10;
        int c = i & 1023;
        int g = c >> 8;       // gate 0..3 (i,f,c,o)
        int m = c & 255;
        g_Wrt[((size_t)(k * 256 + m)) * 4 + g] = Wr[i];
    }
    if (i < 16) g_arr[i] = 0ull;
}

// ---- r2[b][n][u] = sum_t x[b][t][n] * Ue[t][u] ----
__global__ __launch_bounds__(256) void k_r2(const float* __restrict__ x,
                                            const float* __restrict__ Ue) {
    int b = blockIdx.x;
    int ut = blockIdx.y * 64;
    __shared__ float xs[32][128];
    __shared__ float us[32][64];
    int tid = threadIdx.x;
    int n0 = (tid & 31) * 4;
    int u0 = (tid >> 5) * 8;

    float acc[8][4];
#pragma unroll
    for (int j = 0; j < 8; j++)
#pragma unroll
        for (int i = 0; i < 4; i++) acc[j][i] = 0.f;

    for (int kt = 0; kt < T_; kt += 32) {
#pragma unroll
        for (int l = 0; l < 4; l++) {
            int idx = l * 256 + tid;
            int t = idx >> 5, n4 = idx & 31;
            *(float4*)&xs[t][n4 * 4] =
                ((const float4*)x)[(size_t)(b * T_ + kt + t) * 32 + n4];
        }
#pragma unroll
        for (int l = 0; l < 2; l++) {
            int idx = l * 256 + tid;
            int t = idx >> 4, u4 = idx & 15;
            *(float4*)&us[t][u4 * 4] =
                ((const float4*)Ue)[(size_t)(kt + t) * 64 + (ut >> 2) + u4];
        }
        __syncthreads();
#pragma unroll 8
        for (int k = 0; k < 32; k++) {
            float4 x4 = *(const float4*)&xs[k][n0];
            float4 ua = *(const float4*)&us[k][u0];
            float4 ub = *(const float4*)&us[k][u0 + 4];
            float xv[4] = {x4.x, x4.y, x4.z, x4.w};
            float uu[8] = {ua.x, ua.y, ua.z, ua.w, ub.x, ub.y, ub.z, ub.w};
#pragma unroll
            for (int j = 0; j < 8; j++)
#pragma unroll
                for (int i = 0; i < 4; i++) acc[j][i] += xv[i] * uu[j];
        }
        __syncthreads();
    }
#pragma unroll
    for (int i = 0; i < 4; i++) {
        size_t base = ((size_t)(b * N_ + n0 + i)) * T_ + ut + u0;
        *(float4*)&g_r2[base] = make_float4(acc[0][i], acc[1][i], acc[2][i], acc[3][i]);
        *(float4*)&g_r2[base + 4] = make_float4(acc[4][i], acc[5][i], acc[6][i], acc[7][i]);
    }
}

// ---- Xk[t][b][c] = x[b][t][:] @ Wk[:,c] + bias[c]  (FFMA2) ----
__global__ __launch_bounds__(256) void k_xk(const float* __restrict__ x,
                                            const float* __restrict__ Wk,
                                            const float* __restrict__ bias) {
    int rb = blockIdx.x;
    int tid = threadIdx.x;
    int c0 = blockIdx.y * 256 + (tid & 63) * 4;
    int rt = tid >> 6;
    __shared__ float as[32][128];
#pragma unroll
    for (int l = 0; l < 4; l++) {
        int idx = l * 256 + tid;
        int r = idx >> 5, n4 = idx & 31;
        *(float4*)&as[r][n4 * 4] =
            ((const float4*)x)[(size_t)(rb * 32 + r) * 32 + n4];
    }
    __syncthreads();
    unsigned long long acc[8][2];
#pragma unroll
    for (int i = 0; i < 8; i++) { acc[i][0] = 0ull; acc[i][1] = 0ull; }
#pragma unroll 4
    for (int k = 0; k < 128; k++) {
        ulonglong2 wv = *(const ulonglong2*)&Wk[(size_t)k * 1024 + c0];
#pragma unroll
        for (int i = 0; i < 8; i++) {
            unsigned long long a2 = dup2(as[rt * 8 + i][k]);
            acc[i][0] = fma2(a2, wv.x, acc[i][0]);
            acc[i][1] = fma2(a2, wv.y, acc[i][1]);
        }
    }
    float4 bv = ((const float4*)bias)[c0 >> 2];
#pragma unroll
    for (int i = 0; i < 8; i++) {
        int rbt = rb * 32 + rt * 8 + i;
        int b = rbt >> 8;
        int t = rbt & 255;
        float v0, v1, v2, v3;
        unpack2(acc[i][0], v0, v1);
        unpack2(acc[i][1], v2, v3);
        float4 v = make_float4(v0 + bv.x, v1 + bv.y, v2 + bv.z, v3 + bv.w);
        ((float4*)g_Xk)[((size_t)t * B_ + b) * 256 + (c0 >> 2)] = v;
    }
}

// ---- persistent LSTM v3: 8 rows/thread, k-quartered, dup'd H pairs ----
// grid 128 = 16 bx (32 rows) x 8 by (32 m). block 512 = warp(rw 0..3, kq 0..3).
// smem: ws 128KB (Wr slice) + hd 64KB (H pairs, overlaid by partial buffer).
__global__ __launch_bounds__(512, 1) void k_lstm_all() {
    extern __shared__ char smc[];
    float* ws = (float*)smc;                                      // [k][32m][4g]
    unsigned long long* hd = (unsigned long long*)(smc + 131072); // [k][r] (h,h)
    unsigned long long* pp = hd;                                  // partial overlay
    const ulonglong2* wsv = (const ulonglong2*)ws;
    const ulonglong2* hdv2 = (const ulonglong2*)hd;

    int tid = threadIdx.x;
    int bx = blockIdx.x >> 3;   // barrier group (rows bx*32..+31)
    int by = blockIdx.x & 7;    // m cols by*32..+31
    int ml = tid & 31;
    int mg = by * 32 + ml;
    int warp = tid >> 5;
    int rw = warp & 3;          // row group: rows rw*8..+7
    int kq = warp >> 2;         // k quarter: k in [kq*64, +64)
    int r0 = rw * 8 + kq * 2;   // my 2 epilogue rows (local 0..31)

    // weights into smem (once)
#pragma unroll
    for (int l = 0; l < 16; l++) {
        int f = l * 512 + tid;
        int k = f >> 5, mm = f & 31;
        ((float4*)ws)[f] = ((const float4*)g_Wrt)[(size_t)k * 256 + by * 32 + mm];
    }

    // s carry + first Xk prefetch for my 2 rows
    float s2[2];
    float px[2][4];
#pragma unroll
    for (int i = 0; i < 2; i++) {
        int b = bx * 32 + r0 + i;
        s2[i] = g_S[(size_t)b * M_ + mg];
        size_t xo = (size_t)b * FM_ + mg;
        px[i][0] = g_Xk[xo];
        px[i][1] = g_Xk[xo + 256];
        px[i][2] = g_Xk[xo + 512];
        px[i][3] = g_Xk[xo + 768];
    }
    // stage hd[0]: duplicated pairs from g_Ht[0][bx] ([m][r] floats)
#pragma unroll
    for (int l = 0; l < 4; l++) {
        int f = l * 512 + tid;            // f = m*8 + rq
        float4 v = ((const float4*)g_Ht)[(size_t)bx * 2048 + f];
        int p = f * 4;                    // pair base = m*32 + rq*4
        hd[p + 0] = dup2(v.x);
        hd[p + 1] = dup2(v.y);
        hd[p + 2] = dup2(v.z);
        hd[p + 3] = dup2(v.w);
    }
    __syncthreads();

    for (int t = 0; t < T_; t++) {
        unsigned long long aif[8], ago[8];
#pragma unroll
        for (int i = 0; i < 8; i++) { aif[i] = 0ull; ago[i] = 0ull; }

        int kb = kq * 64;
#pragma unroll 4
        for (int kk = 0; kk < 64; kk++) {
            int k = kb + kk;
            ulonglong2 wv = wsv[k * 32 + ml];          // (wi,wf),(wg,wo)
            ulonglong2 h01 = hdv2[k * 16 + rw * 4 + 0]; // rows rw*8+0,1 (dup'd)
            ulonglong2 h23 = hdv2[k * 16 + rw * 4 + 1];
            ulonglong2 h45 = hdv2[k * 16 + rw * 4 + 2];
            ulonglong2 h67 = hdv2[k * 16 + rw * 4 + 3];
            aif[0] = fma2(h01.x, wv.x, aif[0]);  ago[0] = fma2(h01.x, wv.y, ago[0]);
            aif[1] = fma2(h01.y, wv.x, aif[1]);  ago[1] = fma2(h01.y, wv.y, ago[1]);
            aif[2] = fma2(h23.x, wv.x, aif[2]);  ago[2] = fma2(h23.x, wv.y, ago[2]);
            aif[3] = fma2(h23.y, wv.x, aif[3]);  ago[3] = fma2(h23.y, wv.y, ago[3]);
            aif[4] = fma2(h45.x, wv.x, aif[4]);  ago[4] = fma2(h45.x, wv.y, ago[4]);
            aif[5] = fma2(h45.y, wv.x, aif[5]);  ago[5] = fma2(h45.y, wv.y, ago[5]);
            aif[6] = fma2(h67.x, wv.x, aif[6]);  ago[6] = fma2(h67.x, wv.y, ago[6]);
            aif[7] = fma2(h67.y, wv.x, aif[7]);  ago[7] = fma2(h67.y, wv.y, ago[7]);
        }
        __syncthreads();   // all hd reads done before partial overlay writes

        // store partials for the 6 rows I don't own (slot-major: conflict-free)
#pragma unroll
        for (int i = 0; i < 8; i++) {
            int owner = i >> 1;
            if (kq != owner) {
                int cidx = kq - (kq > owner ? 1 : 0);   // 0..2
                int sf = (i * 3 + cidx) * 2;
                pp[(size_t)sf * 128 + rw * 32 + ml] = aif[i];
                pp[(size_t)(sf + 1) * 128 + rw * 32 + ml] = ago[i];
            }
        }
        __syncthreads();

        // combine + epilogue for my 2 rows
        float hv[2];
#pragma unroll
        for (int ii = 0; ii < 2; ii++) {
            int i = kq * 2 + ii;
            unsigned long long zif = aif[i], zgo = ago[i];
#pragma unroll
            for (int c = 0; c < 3; c++) {
                int sf = (i * 3 + c) * 2;
                zif = add2(zif, pp[(size_t)sf * 128 + rw * 32 + ml]);
                zgo = add2(zgo, pp[(size_t)(sf + 1) * 128 + rw * 32 + ml]);
            }
            float zi, zf, zg, zo;
            unpack2(zif, zi, zf);
            unpack2(zgo, zg, zo);
            zi += px[ii][0];
            zf += px[ii][1];
            zg += px[ii][2];
            zo += px[ii][3];
            float ig = sigm(zi), fg = sigm(zf), og = sigm(zo);
            float gg = tanh_e(zg);
            float sn = fg * s2[ii] + ig * gg;
            float hn = og * tanh_e(sn);
            s2[ii] = sn;
            hv[ii] = hn;
            int b = bx * 32 + r0 + ii;
            size_t dn = ((size_t)(t + 1) * B_ + b) * M_ + mg;
            g_S[dn] = sn;
            g_H[dn] = hn;
        }
        // transposed store: g_Ht[t+1][bx][mg][r0..r0+1]
        *(float2*)&g_Ht[((((size_t)(t + 1) * 16 + bx) * 256 + mg)) * 32 + r0] =
            make_float2(hv[0], hv[1]);
        // prefetch next step's Xk (lands during spin/stage)
        int tn = (t < T_ - 1) ? t + 1 : t;
#pragma unroll
        for (int ii = 0; ii < 2; ii++) {
            int b = bx * 32 + r0 + ii;
            size_t xo = ((size_t)tn * B_ + b) * FM_ + mg;
            px[ii][0] = g_Xk[xo];
            px[ii][1] = g_Xk[xo + 256];
            px[ii][2] = g_Xk[xo + 512];
            px[ii][3] = g_Xk[xo + 768];
        }
        __syncthreads();   // all stores + pp reads done before arrive/overlay reuse

        if (tid == 0) {
            __threadfence();
            atomicAdd(&g_arr[bx], 1ull);
        }
        unsigned long long tgt = 8ull * (unsigned long long)(t + 1);
        while (*((volatile unsigned long long*)&g_arr[bx]) < tgt) {}

        // restage hd from g_Ht[t+1][bx]
#pragma unroll
        for (int l = 0; l < 4; l++) {
            int f = l * 512 + tid;
            float4 v = ((const float4*)g_Ht)[((size_t)(t + 1) * 16 + bx) * 2048 + f];
            int p = f * 4;
            hd[p + 0] = dup2(v.x);
            hd[p + 1] = dup2(v.y);
            hd[p + 2] = dup2(v.z);
            hd[p + 3] = dup2(v.w);
        }
        __syncthreads();
    }
}

// ---- R1[tau][b][u] = concat(H,S)[tau][b] @ We[:,u]  (FFMA2) ----
__global__ __launch_bounds__(256) void k_R1(const float* __restrict__ We) {
    int rb = blockIdx.x;
    int tid = threadIdx.x;
    int u0 = (tid & 63) * 4;
    int rt = tid >> 6;
    __shared__ float as[32][64];
    unsigned long long acc[8][2];
#pragma unroll
    for (int i = 0; i < 8; i++) { acc[i][0] = 0ull; acc[i][1] = 0ull; }

    for (int ch = 0; ch < 8; ch++) {
        const float* src = (ch < 4) ? g_H : g_S;
        int boff = (ch & 3) * 16;
        __syncthreads();
#pragma unroll
        for (int l = 0; l < 2; l++) {
            int idx = l * 256 + tid;
            int r = idx >> 4, j4 = idx & 15;
            *(float4*)&as[r][j4 * 4] =
                ((const float4*)src)[(size_t)(rb * 32 + r) * 64 + boff + j4];
        }
        __syncthreads();
#pragma unroll 4
        for (int kk = 0; kk < 64; kk++) {
            ulonglong2 wv = *(const ulonglong2*)&We[(size_t)(ch * 64 + kk) * 256 + u0];
#pragma unroll
            for (int i = 0; i < 8; i++) {
                unsigned long long a2 = dup2(as[rt * 8 + i][kk]);
                acc[i][0] = fma2(a2, wv.x, acc[i][0]);
                acc[i][1] = fma2(a2, wv.y, acc[i][1]);
            }
        }
    }
#pragma unroll
    for (int i = 0; i < 8; i++) {
        float v0, v1, v2, v3;
        unpack2(acc[i][0], v0, v1);
        unpack2(acc[i][1], v2, v3);
        ((float4*)g_R1)[(size_t)(rb * 32 + rt * 8 + i) * 64 + (u0 >> 2)] =
            make_float4(v0, v1, v2, v3);
    }
}

// ---- fused: e = tanh(R1 + r2) @ ve ; softmax over n ; out = alpha * x ----
__global__ __launch_bounds__(512) void k_e(const float* __restrict__ x,
                                           const float* __restrict__ ve,
                                           float* __restrict__ out) {
    extern __shared__ float r2s[];   // 128 * 260 floats
    __shared__ float r1s[4][256];
    __shared__ float ves[256];
    __shared__ float redm[16];
    __shared__ float reds[16];
    int b = blockIdx.x;
    int tau0 = blockIdx.y * 32;
    int tid = threadIdx.x;
    int lane = tid & 31;
    int warp = tid >> 5;
    int q = tid >> 7;
    int n = tid & 127;

    if (tid < 256) ves[tid] = ve[tid];
#pragma unroll
    for (int l = 0; l < 16; l++) {
        int idx = l * 512 + tid;
        int nn = idx >> 6, u4 = idx & 63;
        float4 v = ((const float4*)g_r2)[(size_t)(b * N_ + nn) * 64 + u4];
        *(float4*)&r2s[nn * 260 + u4 * 4] = v;
    }
    __syncthreads();
    const float* rp = &r2s[n * 260];

    for (int ti = 0; ti < 8; ti++) {
#pragma unroll
        for (int l = 0; l < 2; l++) {
            int idx = l * 512 + tid;
            int wh = idx >> 8, u = idx & 255;
            r1s[wh][u] = g_R1[((size_t)(tau0 + ti * 4 + wh) * B_ + b) * T_ + u];
        }
        __syncthreads();
        const float* r1p = r1s[q];
        float acc0 = 0.f, acc1 = 0.f;
#pragma unroll 4
        for (int u4 = 0; u4 < 64; u4++) {
            float4 rv = *(const float4*)&rp[u4 * 4];
            float4 r1 = *(const float4*)&r1p[u4 * 4];
            float4 vv = *(const float4*)&ves[u4 * 4];
            acc0 += tanh_fast(r1.x + rv.x) * vv.x;
            acc1 += tanh_fast(r1.y + rv.y) * vv.y;
            acc0 += tanh_fast(r1.z + rv.z) * vv.z;
            acc1 += tanh_fast(r1.w + rv.w) * vv.w;
        }
        float e = acc0 + acc1;

        float mx = e;
#pragma unroll
        for (int off = 16; off >= 1; off >>= 1)
            mx = fmaxf(mx, __shfl_xor_sync(0xffffffffu, mx, off));
        if (lane == 0) redm[warp] = mx;
        __syncthreads();
        mx = fmaxf(fmaxf(redm[q * 4], redm[q * 4 + 1]),
                   fmaxf(redm[q * 4 + 2], redm[q * 4 + 3]));
        float ex = __expf(e - mx);
        float sm = ex;
#pragma unroll
        for (int off = 16; off >= 1; off >>= 1)
            sm += __shfl_xor_sync(0xffffffffu, sm, off);
        if (lane == 0) reds[warp] = sm;
        __syncthreads();
        sm = reds[q * 4] + reds[q * 4 + 1] + reds[q * 4 + 2] + reds[q * 4 + 3];
        float alpha = ex / sm;

        int tau = tau0 + ti * 4 + q;
        size_t oi = ((size_t)b * T_ + tau) * N_ + n;
        out[oi] = alpha * x[oi];
        __syncthreads();
    }
}

extern "C" void kernel_launch(void* const* d_in, const int* in_sizes, int n_in,
                              void* d_out, int out_size) {
    const float* x  = (const float*)d_in[0];
    const float* s  = (const float*)d_in[1];
    const float* h  = (const float*)d_in[2];
    const float* We = (const float*)d_in[3];
    const float* Ue = (const float*)d_in[4];
    const float* ve = (const float*)d_in[5];
    const float* Wk = (const float*)d_in[6];
    const float* Wr = (const float*)d_in[7];
    const float* bb = (const float*)d_in[8];
    float* out = (float*)d_out;
    (void)in_sizes; (void)n_in; (void)out_size;

    k_init<<<1024, 256>>>(s, h, Wr);
    k_r2<<<dim3(B_, 4), 256>>>(x, Ue);
    k_xk<<<dim3(4096, 4), 256>>>(x, Wk, bb);

    const int SML = 131072 + 65536;  // 128KB weights + 64KB dup'd H / partials
    cudaFuncSetAttribute(k_lstm_all, cudaFuncAttributeMaxDynamicSharedMemorySize, SML);
    k_lstm_all<<<GRID_LSTM, 512, SML>>>();

    k_R1<<<4096, 256>>>(We);

    const int SME = 128 * 260 * (int)sizeof(float);
    cudaFuncSetAttribute(k_e, cudaFuncAttributeMaxDynamicSharedMemorySize, SME);
    k_e<<<dim3(B_, 8), 512, SME>>>(x, ve, out);
}